// round 1
// baseline (speedup 1.0000x reference)
#include <cuda_runtime.h>

// Problem constants (fixed shapes from reference setup_inputs)
#define BB    32        // batch
#define TT    4000      // frames per batch
#define NB    65        // nbands (rfft bins for n=129)
#define LF    129       // FIR length = 2*NB-1
#define FS    80        // framesize (hop)
#define FPB   16        // frames per block tile
#define EF    18        // extended frames staged per block (2 lookback)
#define TILES 250       // TT / FPB
#define OUTW  320000    // TT*FS (trimmed output width per batch)
#define WROW  136       // padded firwin row stride: 3 zero prefix + 129 + 3 zero suffix + 1
#define NTHR  256

// Constant tables computed on device each launch (graph-capturable, deterministic)
__device__ float g_T[NB * NB];     // T[d][k]: zp[d] = sum_k H[k]*T[d][k]
__device__ float g_hann[LF];

__global__ void init_tables_k() {
    int i = blockIdx.x * blockDim.x + threadIdx.x;
    if (i < NB * NB) {
        int d = i / NB, k = i - (i / NB) * NB;
        int m = (k * d) % LF;
        double c = cos(6.283185307179586476925286766559 * (double)m / 129.0);
        g_T[i] = (k == 0) ? (1.0f / 129.0f) : (float)((2.0 / 129.0) * c);
        if (i < LF) {
            g_hann[i] = (float)(0.5 * (1.0 - cos(6.283185307179586476925286766559 * (double)i / 129.0)));
        }
    }
}

__global__ void __launch_bounds__(NTHR)
fng_main(const float* __restrict__ H, const float* __restrict__ noise,
         float* __restrict__ out) {
    __shared__ float sT[NB * NB];                 // 16900 B
    __shared__ float sH[EF * NB];                 // 4680 B
    __shared__ float sZ[EF * NB];                 // 4680 B  (zero-phase half IR per frame)
    __shared__ float sW[EF * WROW];               // 9792 B  (padded firwin rows)
    __shared__ float sX[EF * FS + (EF * FS) / 32];// 5940 B  (swizzled noise samples)

    const int tid  = threadIdx.x;
    const int b    = blockIdx.x / TILES;
    const int tile = blockIdx.x - b * TILES;
    const int t0   = tile * FPB;

    // ---- stage cosine table (L2-resident broadcast) ----
    for (int i = tid; i < NB * NB; i += NTHR) sT[i] = g_T[i];

    // ---- stage H for frames t0-2 .. t0+15 (zero for t<0) ----
    for (int i = tid; i < EF * NB; i += NTHR) {
        int f = i / NB;
        int te = t0 - 2 + f;
        float v = 0.0f;
        if (te >= 0) v = H[((size_t)b * TT + te) * NB + (i - f * NB)];
        sH[i] = v;
    }

    // ---- stage x = 2*noise - 1, swizzled so stride-4 lane access is conflict-free ----
    for (int i = tid; i < EF * FS; i += NTHR) {
        int f = i / FS;
        int te = t0 - 2 + f;
        float v = 0.0f;
        if (te >= 0) v = 2.0f * noise[((size_t)b * TT + te) * FS + (i - f * FS)] - 1.0f;
        sX[i + (i >> 5)] = v;
    }
    __syncthreads();

    // ---- zp[f][d] = sum_k sH[f][k] * sT[d][k], 2f x 2d register blocking ----
    // slots: 9 f-pairs (f, f+9) x 33 d-pairs (d, d+33) = 297
    for (int s = tid; s < 297; s += NTHR) {
        int fp = s / 33;
        int dp = s - fp * 33;
        int f0 = fp, f1 = fp + 9;
        int d0 = dp, d1 = dp + 33;
        bool d1ok = (d1 < NB);
        const float* h0 = &sH[f0 * NB];
        const float* h1 = &sH[f1 * NB];
        const float* tr0 = &sT[d0 * NB];
        const float* tr1 = &sT[(d1ok ? d1 : d0) * NB];
        float a00 = 0.f, a01 = 0.f, a10 = 0.f, a11 = 0.f;
        #pragma unroll 5
        for (int k = 0; k < NB; ++k) {
            float hv0 = h0[k], hv1 = h1[k];
            float tv0 = tr0[k], tv1 = tr1[k];
            a00 = fmaf(hv0, tv0, a00);
            a01 = fmaf(hv0, tv1, a01);
            a10 = fmaf(hv1, tv0, a10);
            a11 = fmaf(hv1, tv1, a11);
        }
        sZ[f0 * NB + d0] = a00;
        sZ[f1 * NB + d0] = a10;
        if (d1ok) { sZ[f0 * NB + d1] = a01; sZ[f1 * NB + d1] = a11; }
    }
    __syncthreads();

    // ---- expand to padded firwin rows: sW[f][3+j] = zp[f][|j-64|]*hann[j], pads = 0 ----
    for (int i = tid; i < EF * WROW; i += NTHR) {
        int f = i / WROW;
        int jj = i - f * WROW;
        int j = jj - 3;
        float v = 0.0f;
        if ((unsigned)j <= 128u) {
            int d = j - 64; d = (d < 0) ? -d : d;
            v = sZ[f * NB + d] * g_hann[j];
        }
        sW[i] = v;
    }
    __syncthreads();

    // ---- conv + overlap-add gather ----
    // Local coords: sl = s_global - (80*t0 - 160), staged range [0, 1440).
    // Thread group g owns 4 consecutive pre-trim outputs q = 80*t0 + 4g + r.
    const int groups = (tile == TILES - 1) ? 336 : 320;
    for (int g = tid; g < groups; g += NTHR) {
        if (tile == 0 && g < 16) continue;  // trimmed head (p < 0)
        int ql  = g * 4;
        int slh = min(ql + 163, EF * FS - 1);
        int sll = ql + 32;
        int f   = slh / FS;
        int ifr = slh - f * FS;
        int jb  = ql + 160 - slh;           // j for r=0 at sl=slh (>= -3)
        const float* wp = &sW[f * WROW + 3 + jb];
        float a0 = 0.f, a1 = 0.f, a2 = 0.f, a3 = 0.f;
        int n  = slh - sll + 1;
        int sl = slh;
        #pragma unroll 4
        for (int it = 0; it < n; ++it) {
            float xv = sX[sl + (sl >> 5)];
            float w0 = wp[0], w1 = wp[1], w2 = wp[2], w3 = wp[3];
            a0 = fmaf(xv, w0, a0);
            a1 = fmaf(xv, w1, a1);
            a2 = fmaf(xv, w2, a2);
            a3 = fmaf(xv, w3, a3);
            --sl; ++wp; --ifr;
            if (ifr < 0) { ifr = FS - 1; wp -= WROW; }
        }
        int p = t0 * FS + ql - 64;          // trimmed output position, multiple of 4
        float4 v = make_float4(a0, a1, a2, a3);
        *reinterpret_cast<float4*>(&out[(size_t)b * OUTW + p]) = v;
    }
}

extern "C" void kernel_launch(void* const* d_in, const int* in_sizes, int n_in,
                              void* d_out, int out_size) {
    (void)in_sizes; (void)n_in; (void)out_size;
    const float* H     = (const float*)d_in[0];
    const float* noise = (const float*)d_in[1];
    float* out         = (float*)d_out;

    init_tables_k<<<17, 256>>>();
    fng_main<<<BB * TILES, NTHR>>>(H, noise, out);
}

// round 2
// speedup vs baseline: 1.3138x; 1.3138x over previous
#include <cuda_runtime.h>

// Fixed shapes from reference setup_inputs
#define BB    32        // batch
#define TT    4000      // frames per batch
#define NB    65        // nbands
#define LF    129       // FIR length = 2*NB-1
#define FS    80        // framesize (hop)
#define FPB   25        // frames per block tile
#define EF    28        // staged frames (t0-2 .. t0+25)
#define TILES 160       // TT / FPB
#define OUTW  320000    // TT*FS
#define WROW  147       // padded firwin row stride (147 mod 32 = 19 -> 5 rows bank-disjoint)
#define NTHR  256

__device__ float g_T[NB * NB];     // zp[d] = sum_k H[k]*T[d][k]
__device__ float g_hann[LF];

__global__ void init_tables_k() {
    int i = blockIdx.x * blockDim.x + threadIdx.x;
    if (i < NB * NB) {
        int d = i / NB, k = i - (i / NB) * NB;
        int m = (k * d) % LF;
        double c = cos(6.283185307179586476925286766559 * (double)m / 129.0);
        g_T[i] = (k == 0) ? (1.0f / 129.0f) : (float)((2.0 / 129.0) * c);
        if (i < LF)
            g_hann[i] = (float)(0.5 * (1.0 - cos(6.283185307179586476925286766559 * (double)i / 129.0)));
    }
}

__global__ void __launch_bounds__(NTHR)
fng_main(const float* __restrict__ H, const float* __restrict__ noise,
         float* __restrict__ out) {
    __shared__ float sH[EF * NB];                       // 7280 B
    __shared__ float sZ[EF * NB];                       // 7280 B
    __shared__ float sW[EF * WROW];                     // 16464 B (row: [0..7]=0, [8..136]=j0..128, [137..146]=0)
    __shared__ float sX[EF * FS + (EF * FS) / 32 + 4];  // 9256 B (swizzled)

    const int tid  = threadIdx.x;
    const int b    = blockIdx.x / TILES;
    const int tile = blockIdx.x - b * TILES;
    const int t0   = tile * FPB;

    // ---- stage H rows and x = 2*noise-1 (zeros outside [0,TT)) ----
    for (int i = tid; i < EF * NB; i += NTHR) {
        int f = i / NB;
        int te = t0 - 2 + f;
        float v = 0.0f;
        if (te >= 0 && te < TT) v = H[((size_t)b * TT + te) * NB + (i - f * NB)];
        sH[i] = v;
    }
    for (int i = tid; i < EF * FS; i += NTHR) {
        int f = i / FS;
        int te = t0 - 2 + f;
        float v = 0.0f;
        if (te >= 0 && te < TT) v = 2.0f * noise[((size_t)b * TT + te) * FS + (i - f * FS)] - 1.0f;
        sX[i + (i >> 5)] = v;
    }
    __syncthreads();

    // ---- zp[f][d] = sum_k sH[f][k] * T[d][k]; 2f x 4d register blocking, T from L2 ----
    if (tid < 238) {                           // 14 f-pairs x 17 d-quads
        int fq = tid / 17;
        int dq = tid - fq * 17;
        int f0 = fq, f1 = fq + 14;
        int d0 = dq * 4;
        const float* h0 = &sH[f0 * NB];
        const float* h1 = &sH[f1 * NB];
        const float* tp0 = &g_T[min(d0 + 0, NB - 1) * NB];
        const float* tp1 = &g_T[min(d0 + 1, NB - 1) * NB];
        const float* tp2 = &g_T[min(d0 + 2, NB - 1) * NB];
        const float* tp3 = &g_T[min(d0 + 3, NB - 1) * NB];
        float a00=0,a01=0,a02=0,a03=0,a10=0,a11=0,a12=0,a13=0;
        #pragma unroll 5
        for (int k = 0; k < NB; ++k) {
            float hv0 = h0[k], hv1 = h1[k];
            float tv0 = __ldg(tp0 + k), tv1 = __ldg(tp1 + k);
            float tv2 = __ldg(tp2 + k), tv3 = __ldg(tp3 + k);
            a00 = fmaf(hv0, tv0, a00); a01 = fmaf(hv0, tv1, a01);
            a02 = fmaf(hv0, tv2, a02); a03 = fmaf(hv0, tv3, a03);
            a10 = fmaf(hv1, tv0, a10); a11 = fmaf(hv1, tv1, a11);
            a12 = fmaf(hv1, tv2, a12); a13 = fmaf(hv1, tv3, a13);
        }
        float* z0 = &sZ[f0 * NB + d0];
        float* z1 = &sZ[f1 * NB + d0];
        z0[0] = a00; z1[0] = a10;
        if (d0 + 1 < NB) { z0[1] = a01; z1[1] = a11; }
        if (d0 + 2 < NB) { z0[2] = a02; z1[2] = a12; }
        if (d0 + 3 < NB) { z0[3] = a03; z1[3] = a13; }
    }
    __syncthreads();

    // ---- expand padded firwin rows: sW[f][8+j] = zp[f][|j-64|]*hann[j] ----
    for (int i = tid; i < EF * WROW; i += NTHR) {
        int f = i / WROW;
        int j = (i - f * WROW) - 8;
        float v = 0.0f;
        if ((unsigned)j <= 128u) {
            int d = j - 64; d = (d < 0) ? -d : d;
            v = sZ[f * NB + d] * g_hann[j];
        }
        sW[i] = v;
    }
    __syncthreads();

    // ---- conv + OLA: each thread owns 8 consecutive pre-trim outputs Q0..Q0+7 ----
    // Q0 = 80*t0 + 8g; samples s in [Q0-128, Q0+7]; local sl = s - (80*t0 - 160).
    // 17 chunks of 8 samples; a chunk never straddles a frame or a 32-swizzle block.
    const int groups = (tile == TILES - 1) ? 258 : 250;
    for (int g = tid; g < groups; g += NTHR) {
        if (tile == 0 && g < 8) continue;      // trimmed head
        const int ql0 = g * 8;
        const int sl0 = ql0 + 32;
        int f = sl0 / FS;
        int rem = sl0 - f * FS;
        int cb = (rem == 0) ? 10 : ((FS - rem) >> 3);   // next frame-boundary chunk
        const float* wr = &sW[f * WROW];
        int woff = 135;                                  // = 135 - 8c
        float acc[8] = {0,0,0,0,0,0,0,0};
        float W[8];
        #pragma unroll
        for (int m = 0; m < 8; ++m) W[m] = wr[136 + m];  // window slot m = wr[136-8c+m]

        for (int c = 0; c < 16; ++c) {
            if (c == cb) {                                // new frame row: reload window
                wr += WROW;
                cb += 10;
                #pragma unroll
                for (int m = 0; m < 8; ++m) W[m] = wr[woff + 1 + m];
            }
            int slc = sl0 + 8 * c;
            const float* xp = &sX[slc + (slc >> 5)];
            #pragma unroll
            for (int u = 0; u < 8; ++u) {
                float xv = xp[u];
                #pragma unroll
                for (int r = 0; r < 8; ++r)
                    acc[r] = fmaf(xv, W[(r - u + 8) & 7], acc[r]);
                W[(7 - u) & 7] = wr[woff - u];           // slide: load next-lower j
            }
            woff -= 8;
        }
        {   // peeled last chunk (c = 16): skip the out-of-range final slide load
            if (16 == cb) {
                wr += WROW;
                #pragma unroll
                for (int m = 0; m < 8; ++m) W[m] = wr[woff + 1 + m];
            }
            int slc = sl0 + 128;
            const float* xp = &sX[slc + (slc >> 5)];
            #pragma unroll
            for (int u = 0; u < 8; ++u) {
                float xv = xp[u];
                #pragma unroll
                for (int r = 0; r < 8; ++r)
                    acc[r] = fmaf(xv, W[(r - u + 8) & 7], acc[r]);
                if (u < 7) W[(7 - u) & 7] = wr[woff - u];
            }
        }

        int p = t0 * FS + ql0 - 64;            // trimmed position, multiple of 8
        float* op = &out[(size_t)b * OUTW + p];
        *reinterpret_cast<float4*>(op)     = make_float4(acc[0], acc[1], acc[2], acc[3]);
        *reinterpret_cast<float4*>(op + 4) = make_float4(acc[4], acc[5], acc[6], acc[7]);
    }
}

extern "C" void kernel_launch(void* const* d_in, const int* in_sizes, int n_in,
                              void* d_out, int out_size) {
    (void)in_sizes; (void)n_in; (void)out_size;
    const float* H     = (const float*)d_in[0];
    const float* noise = (const float*)d_in[1];
    float* out         = (float*)d_out;

    init_tables_k<<<17, 256>>>();
    fng_main<<<BB * TILES, NTHR>>>(H, noise, out);
}

// round 3
// speedup vs baseline: 1.8421x; 1.4021x over previous
#include <cuda_runtime.h>

// Fixed shapes from reference setup_inputs
#define BB    32        // batch
#define TT    4000      // frames per batch
#define NB    65        // nbands
#define LF    129       // FIR length = 2*NB-1
#define FS    80        // framesize (hop)
#define FPB   25        // frames per block tile (kernel B)
#define EF    28        // staged frames (t0-2 .. t0+25)
#define TILES 160       // TT / FPB
#define OUTW  320000    // TT*FS
#define WROW  147       // padded firwin row stride
#define NTHR  256
#define NFRM  (BB*TT)   // 128000 flat frames
#define ZPST  68        // zp scratch row stride (float4-aligned)
#define ANF   64        // frames per block in kernel A

__device__ float g_T[NB * NB];       // zp[d] = sum_k H[k]*T[d][k]
__device__ float g_hann[LF];
__device__ float g_zp[NFRM * ZPST];  // 34.8 MB scratch: zero-phase half-IR per frame

__global__ void init_tables_k() {
    int i = blockIdx.x * blockDim.x + threadIdx.x;
    if (i < NB * NB) {
        int d = i / NB, k = i - (i / NB) * NB;
        int m = (k * d) % LF;
        double c = cos(6.283185307179586476925286766559 * (double)m / 129.0);
        g_T[i] = (k == 0) ? (1.0f / 129.0f) : (float)((2.0 / 129.0) * c);
        if (i < LF)
            g_hann[i] = (float)(0.5 * (1.0 - cos(6.283185307179586476925286766559 * (double)i / 129.0)));
    }
}

// ---------------- Kernel A: zp[n][d] = sum_k H[n][k] * T[d][k] ----------------
// Block: 64 frames. Warp w owns frames f0=8w..f0+7; lane l owns d = l and l+33.
// d = 32 handled by a small epilogue. Layouts use stride 68 so k-chunks of 4 are
// float4-aligned: T loads are per-lane LDS.128 (distinct rows), h loads are
// warp-uniform LDS.128 broadcasts.
__global__ void __launch_bounds__(NTHR)
zp_kernel(const float* __restrict__ H) {
    __shared__ float sTa[NB * ZPST];   // 17680 B
    __shared__ float sHa[ANF * ZPST];  // 17408 B

    const int tid = threadIdx.x;
    const int n0  = blockIdx.x * ANF;

    for (int i = tid; i < NB * NB; i += NTHR) {
        int d = i / NB, k = i - d * NB;
        sTa[d * ZPST + k] = g_T[i];
    }
    for (int i = tid; i < ANF * NB; i += NTHR) {
        int f = i / NB, k = i - f * NB;
        sHa[f * ZPST + k] = H[(size_t)(n0 + f) * NB + k];
    }
    __syncthreads();

    const int w = tid >> 5, l = tid & 31;
    const int f0 = w * 8;
    const float* tr0 = &sTa[l * ZPST];
    const float* tr1 = &sTa[(l + 33) * ZPST];

    float acc0[8] = {0,0,0,0,0,0,0,0};
    float acc1[8] = {0,0,0,0,0,0,0,0};

    #pragma unroll 4
    for (int kc = 0; kc < 16; ++kc) {
        int k0 = kc * 4;
        float4 t0 = *reinterpret_cast<const float4*>(tr0 + k0);
        float4 t1 = *reinterpret_cast<const float4*>(tr1 + k0);
        #pragma unroll
        for (int j = 0; j < 8; ++j) {
            float4 hv = *reinterpret_cast<const float4*>(&sHa[(f0 + j) * ZPST + k0]);
            float a0 = acc0[j], a1 = acc1[j];
            a0 = fmaf(hv.x, t0.x, a0); a1 = fmaf(hv.x, t1.x, a1);
            a0 = fmaf(hv.y, t0.y, a0); a1 = fmaf(hv.y, t1.y, a1);
            a0 = fmaf(hv.z, t0.z, a0); a1 = fmaf(hv.z, t1.z, a1);
            a0 = fmaf(hv.w, t0.w, a0); a1 = fmaf(hv.w, t1.w, a1);
            acc0[j] = a0; acc1[j] = a1;
        }
    }
    {   // k = 64 tail
        float t0s = tr0[64], t1s = tr1[64];
        #pragma unroll
        for (int j = 0; j < 8; ++j) {
            float hs = sHa[(f0 + j) * ZPST + 64];
            acc0[j] = fmaf(hs, t0s, acc0[j]);
            acc1[j] = fmaf(hs, t1s, acc1[j]);
        }
    }
    #pragma unroll
    for (int j = 0; j < 8; ++j) {
        size_t row = (size_t)(n0 + f0 + j) * ZPST;
        g_zp[row + l]      = acc0[j];
        g_zp[row + l + 33] = acc1[j];
    }
    // d = 32 epilogue: threads 0..63, one frame each
    if (tid < ANF) {
        const float* tr = &sTa[32 * ZPST];
        const float* hr = &sHa[tid * ZPST];
        float s = 0.0f;
        #pragma unroll 5
        for (int k = 0; k < NB; ++k) s = fmaf(hr[k], tr[k], s);
        g_zp[(size_t)(n0 + tid) * ZPST + 32] = s;
    }
}

// ---------------- Kernel B: firwin expand + conv + overlap-add ----------------
__global__ void __launch_bounds__(NTHR)
fng_main(const float* __restrict__ noise, float* __restrict__ out) {
    __shared__ float sZ[EF * NB];                       // 7280 B
    __shared__ float sW[EF * WROW];                     // 16464 B
    __shared__ float sX[EF * FS + (EF * FS) / 32 + 4];  // 9256 B

    const int tid  = threadIdx.x;
    const int b    = blockIdx.x / TILES;
    const int tile = blockIdx.x - b * TILES;
    const int t0   = tile * FPB;

    // ---- stage zp rows (coalesced) and x = 2*noise-1 ----
    for (int i = tid; i < EF * NB; i += NTHR) {
        int f = i / NB;
        int te = t0 - 2 + f;
        float v = 0.0f;
        if (te >= 0 && te < TT) v = g_zp[(size_t)(b * TT + te) * ZPST + (i - f * NB)];
        sZ[i] = v;
    }
    for (int i = tid; i < EF * FS; i += NTHR) {
        int f = i / FS;
        int te = t0 - 2 + f;
        float v = 0.0f;
        if (te >= 0 && te < TT) v = 2.0f * noise[((size_t)b * TT + te) * FS + (i - f * FS)] - 1.0f;
        sX[i + (i >> 5)] = v;
    }
    __syncthreads();

    // ---- expand padded firwin rows: sW[f][8+j] = zp[f][|j-64|]*hann[j] ----
    for (int i = tid; i < EF * WROW; i += NTHR) {
        int f = i / WROW;
        int j = (i - f * WROW) - 8;
        float v = 0.0f;
        if ((unsigned)j <= 128u) {
            int d = j - 64; d = (d < 0) ? -d : d;
            v = sZ[f * NB + d] * g_hann[j];
        }
        sW[i] = v;
    }
    __syncthreads();

    // ---- conv + OLA: each thread owns 8 consecutive pre-trim outputs ----
    const int groups = (tile == TILES - 1) ? 258 : 250;
    for (int g = tid; g < groups; g += NTHR) {
        if (tile == 0 && g < 8) continue;      // trimmed head
        const int ql0 = g * 8;
        const int sl0 = ql0 + 32;
        int f = sl0 / FS;
        int rem = sl0 - f * FS;
        int cb = (rem == 0) ? 10 : ((FS - rem) >> 3);   // next frame-boundary chunk
        const float* wr = &sW[f * WROW];
        int woff = 135;
        float acc[8] = {0,0,0,0,0,0,0,0};
        float W[8];
        #pragma unroll
        for (int m = 0; m < 8; ++m) W[m] = wr[136 + m];

        for (int c = 0; c < 16; ++c) {
            if (c == cb) {
                wr += WROW;
                cb += 10;
                #pragma unroll
                for (int m = 0; m < 8; ++m) W[m] = wr[woff + 1 + m];
            }
            int slc = sl0 + 8 * c;
            const float* xp = &sX[slc + (slc >> 5)];
            #pragma unroll
            for (int u = 0; u < 8; ++u) {
                float xv = xp[u];
                #pragma unroll
                for (int r = 0; r < 8; ++r)
                    acc[r] = fmaf(xv, W[(r - u + 8) & 7], acc[r]);
                W[(7 - u) & 7] = wr[woff - u];
            }
            woff -= 8;
        }
        {   // peeled last chunk (c = 16)
            if (16 == cb) {
                wr += WROW;
                #pragma unroll
                for (int m = 0; m < 8; ++m) W[m] = wr[woff + 1 + m];
            }
            int slc = sl0 + 128;
            const float* xp = &sX[slc + (slc >> 5)];
            #pragma unroll
            for (int u = 0; u < 8; ++u) {
                float xv = xp[u];
                #pragma unroll
                for (int r = 0; r < 8; ++r)
                    acc[r] = fmaf(xv, W[(r - u + 8) & 7], acc[r]);
                if (u < 7) W[(7 - u) & 7] = wr[woff - u];
            }
        }

        int p = t0 * FS + ql0 - 64;
        float* op = &out[(size_t)b * OUTW + p];
        *reinterpret_cast<float4*>(op)     = make_float4(acc[0], acc[1], acc[2], acc[3]);
        *reinterpret_cast<float4*>(op + 4) = make_float4(acc[4], acc[5], acc[6], acc[7]);
    }
}

extern "C" void kernel_launch(void* const* d_in, const int* in_sizes, int n_in,
                              void* d_out, int out_size) {
    (void)in_sizes; (void)n_in; (void)out_size;
    const float* H     = (const float*)d_in[0];
    const float* noise = (const float*)d_in[1];
    float* out         = (float*)d_out;

    init_tables_k<<<17, 256>>>();
    zp_kernel<<<NFRM / ANF, NTHR>>>(H);
    fng_main<<<BB * TILES, NTHR>>>(noise, out);
}